// round 1
// baseline (speedup 1.0000x reference)
#include <cuda_runtime.h>
#include <math.h>
#include <stdint.h>

// Problem constants
#define BB 4
#define SS 2048
#define DD 1024
#define HH 16
#define DKH 64

#define MTOT (BB*SS)          // 8192 rows

// ---------------- scratch (static device globals; no allocation) -------------
__device__ float g_Q [MTOT*DD];
__device__ float g_K [MTOT*DD];
__device__ float g_V [MTOT*DD];
__device__ float g_AO[MTOT*DD];

// =============================================================================
// SGEMM with bias epilogue: C[M,N] = A[M,K] @ W[K,N] + bias[N]
// Tile 128x128x8, 256 threads, 8x8 microtile, float4 everywhere.
// =============================================================================
__global__ __launch_bounds__(256) void sgemm_bias_kernel(
    const float* __restrict__ A, const float* __restrict__ W,
    const float* __restrict__ bias, float* __restrict__ C,
    int M, int N, int K)
{
    __shared__ float As[8][132];   // transposed: As[k][m]
    __shared__ float Bs[8][132];   // Bs[k][n]

    const int tid = threadIdx.x;
    const int tx  = tid & 15;
    const int ty  = tid >> 4;
    const int m0  = blockIdx.y << 7;
    const int n0  = blockIdx.x << 7;

    // A tile load mapping: 128 rows x 8 cols = 256 float4
    const int ar = tid >> 1;
    const int ac = (tid & 1) << 2;
    // B tile load mapping: 8 rows x 128 cols = 256 float4
    const int brr = tid >> 5;
    const int bcc = (tid & 31) << 2;

    float acc[8][8];
#pragma unroll
    for (int i = 0; i < 8; i++)
#pragma unroll
        for (int j = 0; j < 8; j++) acc[i][j] = 0.f;

    for (int k0 = 0; k0 < K; k0 += 8) {
        float4 av = *(const float4*)(A + (size_t)(m0 + ar) * K + k0 + ac);
        As[ac + 0][ar] = av.x;
        As[ac + 1][ar] = av.y;
        As[ac + 2][ar] = av.z;
        As[ac + 3][ar] = av.w;

        float4 bv = *(const float4*)(W + (size_t)(k0 + brr) * N + n0 + bcc);
        *(float4*)&Bs[brr][bcc] = bv;

        __syncthreads();

#pragma unroll
        for (int kk = 0; kk < 8; kk++) {
            float4 a0 = *(float4*)&As[kk][(ty << 3) + 0];
            float4 a1 = *(float4*)&As[kk][(ty << 3) + 4];
            float4 b0 = *(float4*)&Bs[kk][(tx << 3) + 0];
            float4 b1 = *(float4*)&Bs[kk][(tx << 3) + 4];
            float ra[8] = {a0.x, a0.y, a0.z, a0.w, a1.x, a1.y, a1.z, a1.w};
            float rb[8] = {b0.x, b0.y, b0.z, b0.w, b1.x, b1.y, b1.z, b1.w};
#pragma unroll
            for (int i = 0; i < 8; i++)
#pragma unroll
                for (int j = 0; j < 8; j++)
                    acc[i][j] += ra[i] * rb[j];
        }
        __syncthreads();
    }

    float4 bi0 = *(const float4*)(bias + n0 + (tx << 3) + 0);
    float4 bi1 = *(const float4*)(bias + n0 + (tx << 3) + 4);

#pragma unroll
    for (int i = 0; i < 8; i++) {
        size_t crow = (size_t)(m0 + (ty << 3) + i);
        float4 c0, c1;
        c0.x = acc[i][0] + bi0.x; c0.y = acc[i][1] + bi0.y;
        c0.z = acc[i][2] + bi0.z; c0.w = acc[i][3] + bi0.w;
        c1.x = acc[i][4] + bi1.x; c1.y = acc[i][5] + bi1.y;
        c1.z = acc[i][6] + bi1.z; c1.w = acc[i][7] + bi1.w;
        *(float4*)(C + crow * N + n0 + (tx << 3) + 0) = c0;
        *(float4*)(C + crow * N + n0 + (tx << 3) + 4) = c1;
    }
}

// =============================================================================
// Flash attention (causal), fp32.
// Grid: (S/64, H, B). Block: 256 threads (16x16), 4x4 microtile over 64x64.
// Tiles: Br=Bc=64, DK=64. Online softmax kept in registers; row statistics
// reduced across the 16 lanes owning a row via __shfl_xor_sync (half-warp).
// Smem: Qs[64][68] + KPs[64][68] (K tile, reused for P) + Vs[64][68] = 52224 B.
// =============================================================================
#define PAD 68

__global__ __launch_bounds__(256) void flash_attn_kernel(
    const float* __restrict__ Q, const float* __restrict__ K,
    const float* __restrict__ V, float* __restrict__ O)
{
    const int qt = blockIdx.x;
    const int h  = blockIdx.y;
    const int b  = blockIdx.z;
    const int tid = threadIdx.x;
    const int tx = tid & 15;
    const int ty = tid >> 4;

    extern __shared__ float sm[];
    float* Qs  = sm;                 // [64][PAD]
    float* KPs = sm + 64 * PAD;      // [64][PAD]  (K tile, later P tile)
    float* Vs  = sm + 2 * 64 * PAD;  // [64][PAD]

    // ---- load Q tile (64 x 64) ----
    const float* Qb = Q + ((size_t)(b * SS + qt * 64)) * DD + h * DKH;
#pragma unroll
    for (int p = 0; p < 4; p++) {
        int e  = p * 256 + tid;        // float4 index, 0..1023
        int r  = e >> 4;
        int c  = (e & 15) << 2;
        *(float4*)&Qs[r * PAD + c] = *(const float4*)(Qb + (size_t)r * DD + c);
    }

    float m_i[4], l_i[4], o_acc[4][4];
#pragma unroll
    for (int a = 0; a < 4; a++) {
        m_i[a] = -INFINITY;
        l_i[a] = 0.f;
#pragma unroll
        for (int c = 0; c < 4; c++) o_acc[a][c] = 0.f;
    }

    for (int kt = 0; kt <= qt; kt++) {
        __syncthreads();  // prior-iter smem reads done; also orders Q stores (iter 0)

        const float* Kb = K + ((size_t)(b * SS + kt * 64)) * DD + h * DKH;
        const float* Vb = V + ((size_t)(b * SS + kt * 64)) * DD + h * DKH;
#pragma unroll
        for (int p = 0; p < 4; p++) {
            int e = p * 256 + tid;
            int r = e >> 4;
            int c = (e & 15) << 2;
            *(float4*)&KPs[r * PAD + c] = *(const float4*)(Kb + (size_t)r * DD + c);
            *(float4*)&Vs [r * PAD + c] = *(const float4*)(Vb + (size_t)r * DD + c);
        }
        __syncthreads();

        // ---- S = Q K^T / 8 ----
        float s[4][4];
#pragma unroll
        for (int a = 0; a < 4; a++)
#pragma unroll
            for (int c = 0; c < 4; c++) s[a][c] = 0.f;

#pragma unroll
        for (int k4 = 0; k4 < 16; k4++) {
            float4 qa[4], kb[4];
#pragma unroll
            for (int a = 0; a < 4; a++)
                qa[a] = *(float4*)&Qs[(ty * 4 + a) * PAD + k4 * 4];
#pragma unroll
            for (int c = 0; c < 4; c++)
                kb[c] = *(float4*)&KPs[(tx * 4 + c) * PAD + k4 * 4];
#pragma unroll
            for (int a = 0; a < 4; a++)
#pragma unroll
                for (int c = 0; c < 4; c++) {
                    s[a][c] += qa[a].x * kb[c].x;
                    s[a][c] += qa[a].y * kb[c].y;
                    s[a][c] += qa[a].z * kb[c].z;
                    s[a][c] += qa[a].w * kb[c].w;
                }
        }

        const bool diag = (kt == qt);
#pragma unroll
        for (int a = 0; a < 4; a++)
#pragma unroll
            for (int c = 0; c < 4; c++) {
                s[a][c] *= 0.125f;  // 1/sqrt(64)
                if (diag && (tx * 4 + c) > (ty * 4 + a)) s[a][c] = -1e30f;
            }

        // ---- online softmax (register stats, half-warp reductions) ----
        float mt[4];
#pragma unroll
        for (int a = 0; a < 4; a++)
            mt[a] = fmaxf(fmaxf(s[a][0], s[a][1]), fmaxf(s[a][2], s[a][3]));
#pragma unroll
        for (int off = 8; off >= 1; off >>= 1)
#pragma unroll
            for (int a = 0; a < 4; a++)
                mt[a] = fmaxf(mt[a], __shfl_xor_sync(0xffffffffu, mt[a], off));

        float alpha[4], rs[4];
#pragma unroll
        for (int a = 0; a < 4; a++) {
            float mn = fmaxf(m_i[a], mt[a]);
            alpha[a] = __expf(m_i[a] - mn);
            m_i[a] = mn;
            rs[a] = 0.f;
#pragma unroll
            for (int c = 0; c < 4; c++) {
                s[a][c] = __expf(s[a][c] - mn);
                rs[a] += s[a][c];
            }
        }
#pragma unroll
        for (int off = 8; off >= 1; off >>= 1)
#pragma unroll
            for (int a = 0; a < 4; a++)
                rs[a] += __shfl_xor_sync(0xffffffffu, rs[a], off);
#pragma unroll
        for (int a = 0; a < 4; a++) {
            l_i[a] = l_i[a] * alpha[a] + rs[a];
#pragma unroll
            for (int c = 0; c < 4; c++) o_acc[a][c] *= alpha[a];
        }

        // ---- write P into KPs (K tile no longer needed) ----
        __syncthreads();
#pragma unroll
        for (int a = 0; a < 4; a++) {
            float4 pv = make_float4(s[a][0], s[a][1], s[a][2], s[a][3]);
            *(float4*)&KPs[(ty * 4 + a) * PAD + tx * 4] = pv;
        }
        __syncthreads();

        // ---- O += P @ V ----
#pragma unroll
        for (int k4 = 0; k4 < 16; k4++) {
            float4 pa[4];
#pragma unroll
            for (int a = 0; a < 4; a++)
                pa[a] = *(float4*)&KPs[(ty * 4 + a) * PAD + k4 * 4];
#pragma unroll
            for (int u = 0; u < 4; u++) {
                float4 vv = *(float4*)&Vs[(k4 * 4 + u) * PAD + tx * 4];
                float vb[4] = {vv.x, vv.y, vv.z, vv.w};
#pragma unroll
                for (int a = 0; a < 4; a++) {
                    float pv = ((const float*)&pa[a])[u];
#pragma unroll
                    for (int c = 0; c < 4; c++)
                        o_acc[a][c] += pv * vb[c];
                }
            }
        }
    }

    // ---- epilogue ----
#pragma unroll
    for (int a = 0; a < 4; a++) {
        float inv = 1.f / l_i[a];
        int rg = qt * 64 + ty * 4 + a;
        float4 ov = make_float4(o_acc[a][0] * inv, o_acc[a][1] * inv,
                                o_acc[a][2] * inv, o_acc[a][3] * inv);
        *(float4*)(O + ((size_t)(b * SS + rg)) * DD + h * DKH + tx * 4) = ov;
    }
}

// =============================================================================
// Launch
// =============================================================================
extern "C" void kernel_launch(void* const* d_in, const int* in_sizes, int n_in,
                              void* d_out, int out_size)
{
    // input order: x, q, k, v, mask, wq, bq, wk, bk, wv, bv, wo, bo
    const float* q  = (const float*)d_in[1];
    const float* k  = (const float*)d_in[2];
    const float* v  = (const float*)d_in[3];
    const float* wq = (const float*)d_in[5];
    const float* bq = (const float*)d_in[6];
    const float* wk = (const float*)d_in[7];
    const float* bk = (const float*)d_in[8];
    const float* wv = (const float*)d_in[9];
    const float* bv = (const float*)d_in[10];
    const float* wo = (const float*)d_in[11];
    const float* bo = (const float*)d_in[12];
    float* out = (float*)d_out;

    float *gq, *gk, *gv, *gao;
    cudaGetSymbolAddress((void**)&gq,  g_Q);
    cudaGetSymbolAddress((void**)&gk,  g_K);
    cudaGetSymbolAddress((void**)&gv,  g_V);
    cudaGetSymbolAddress((void**)&gao, g_AO);

    const int smem_attn = 3 * 64 * PAD * sizeof(float);  // 52224 B
    cudaFuncSetAttribute(flash_attn_kernel,
                         cudaFuncAttributeMaxDynamicSharedMemorySize, smem_attn);

    dim3 gblk(256);
    dim3 ggrid(DD / 128, MTOT / 128);   // (8, 64)

    sgemm_bias_kernel<<<ggrid, gblk>>>(q, wq, bq, gq, MTOT, DD, DD);
    sgemm_bias_kernel<<<ggrid, gblk>>>(k, wk, bk, gk, MTOT, DD, DD);
    sgemm_bias_kernel<<<ggrid, gblk>>>(v, wv, bv, gv, MTOT, DD, DD);

    dim3 agrid(SS / 64, HH, BB);        // (32, 16, 4)
    flash_attn_kernel<<<agrid, gblk, smem_attn>>>(gq, gk, gv, gao);

    sgemm_bias_kernel<<<ggrid, gblk>>>(gao, wo, bo, out, MTOT, DD, DD);
}

// round 2
// speedup vs baseline: 1.5139x; 1.5139x over previous
#include <cuda_runtime.h>
#include <math.h>
#include <stdint.h>

// Problem constants
#define BB 4
#define SS 2048
#define DD 1024
#define HH 16
#define DKH 64
#define MTOT (BB*SS)          // 8192 rows

// ---------------- scratch (static device globals; no allocation) -------------
__device__ float g_Q [MTOT*DD];
__device__ float g_K [MTOT*DD];
__device__ float g_V [MTOT*DD];
__device__ float g_AO[MTOT*DD];
__device__ float g_Tq[MTOT*DD];
__device__ float g_Tk[MTOT*DD];
__device__ float g_Tv[MTOT*DD];
__device__ float g_Wq[DD*DD];
__device__ float g_Wk[DD*DD];
__device__ float g_Wv[DD*DD];
__device__ float g_Wo[DD*DD];

// ---------------- tf32 helpers ----------------------------------------------
__device__ __forceinline__ float tf32r(float x) {
    uint32_t u;
    asm("cvt.rna.tf32.f32 %0, %1;" : "=r"(u) : "f"(x));
    return __uint_as_float(u);
}

__global__ __launch_bounds__(256) void round_tf32_kernel(
    const float* __restrict__ in, float* __restrict__ out, int n4)
{
    int i = blockIdx.x * blockDim.x + threadIdx.x;
    if (i < n4) {
        float4 v = ((const float4*)in)[i];
        v.x = tf32r(v.x); v.y = tf32r(v.y);
        v.z = tf32r(v.z); v.w = tf32r(v.w);
        ((float4*)out)[i] = v;
    }
}

// ---------------- cp.async helpers -------------------------------------------
__device__ __forceinline__ void cpa16(uint32_t smem, const void* gmem) {
    asm volatile("cp.async.cg.shared.global [%0], [%1], 16;" :: "r"(smem), "l"(gmem));
}
__device__ __forceinline__ void cpa_commit() {
    asm volatile("cp.async.commit_group;");
}
__device__ __forceinline__ void cpa_wait0() {
    asm volatile("cp.async.wait_group 0;");
}

// =============================================================================
// TF32 tensor-core GEMM with bias: C[M,N] = A[M,K] @ W[K,N] + bias[N]
// Block 128x128x16, 256 threads (8 warps, warp tile 32x64), mma.m16n8k8.tf32,
// cp.async double-buffered smem. Operands must be pre-rounded to tf32.
// Smem pitches: A rows pitch 20 floats, B rows pitch 136 floats -> the
// fragment LDS patterns are bank-conflict-free (verified mod-32 arithmetic).
// =============================================================================
#define APITCH 20
#define BPITCH 136

__global__ __launch_bounds__(256) void gemm_tf32_bias(
    const float* __restrict__ A, const float* __restrict__ W,
    const float* __restrict__ bias, float* __restrict__ C,
    int M, int N, int K)
{
    __shared__ float As[2][128 * APITCH];   // [buf][row*APITCH + k]
    __shared__ float Bs[2][16 * BPITCH];    // [buf][k*BPITCH + n]

    const int tid  = threadIdx.x;
    const int wid  = tid >> 5;
    const int lane = tid & 31;
    const int g    = lane >> 2;   // 0..7
    const int t    = lane & 3;    // 0..3
    const int wm   = (wid & 3) << 5;   // 0,32,64,96
    const int wn   = (wid >> 2) << 6;  // 0,64
    const int m0   = blockIdx.y << 7;
    const int n0   = blockIdx.x << 7;

    // load-index precompute (2 chunks each for A and B per thread)
    const int ar0 = tid >> 1;                 // chunk mapping A: 512 chunks
    // chunk c = i*256+tid: row=c>>2, kchunk=(c&3)<<2
    float c[2][8][4];
#pragma unroll
    for (int mi = 0; mi < 2; mi++)
#pragma unroll
        for (int ni = 0; ni < 8; ni++)
#pragma unroll
            for (int j = 0; j < 4; j++) c[mi][ni][j] = 0.f;

    const int NK = K >> 4;   // 16 per iter

    // ---- tile loader ----
    auto loadTile = [&](int kt, int buf) {
        const int k0 = kt << 4;
#pragma unroll
        for (int i = 0; i < 2; i++) {
            int ca = i * 256 + tid;
            int arr = ca >> 2, ak = (ca & 3) << 2;
            cpa16((uint32_t)__cvta_generic_to_shared(&As[buf][arr * APITCH + ak]),
                  A + (size_t)(m0 + arr) * K + k0 + ak);
            int brr = ca >> 5, bn = (ca & 31) << 2;
            cpa16((uint32_t)__cvta_generic_to_shared(&Bs[buf][brr * BPITCH + bn]),
                  W + (size_t)(k0 + brr) * N + n0 + bn);
        }
        cpa_commit();
    };

    loadTile(0, 0);

    for (int kt = 0; kt < NK; kt++) {
        const int buf = kt & 1;
        cpa_wait0();
        __syncthreads();
        if (kt + 1 < NK) loadTile(kt + 1, buf ^ 1);

        const float* as = As[buf];
        const float* bs = Bs[buf];

#pragma unroll
        for (int ks = 0; ks < 16; ks += 8) {
            uint32_t a[2][4], b[8][2];
#pragma unroll
            for (int mi = 0; mi < 2; mi++) {
                int mr = wm + (mi << 4) + g;
                a[mi][0] = __float_as_uint(as[(mr    ) * APITCH + ks + t    ]);
                a[mi][1] = __float_as_uint(as[(mr + 8) * APITCH + ks + t    ]);
                a[mi][2] = __float_as_uint(as[(mr    ) * APITCH + ks + t + 4]);
                a[mi][3] = __float_as_uint(as[(mr + 8) * APITCH + ks + t + 4]);
            }
#pragma unroll
            for (int ni = 0; ni < 8; ni++) {
                int nc = wn + (ni << 3) + g;
                b[ni][0] = __float_as_uint(bs[(ks + t    ) * BPITCH + nc]);
                b[ni][1] = __float_as_uint(bs[(ks + t + 4) * BPITCH + nc]);
            }
#pragma unroll
            for (int mi = 0; mi < 2; mi++)
#pragma unroll
                for (int ni = 0; ni < 8; ni++) {
                    asm volatile(
                        "mma.sync.aligned.m16n8k8.row.col.f32.tf32.tf32.f32 "
                        "{%0,%1,%2,%3}, {%4,%5,%6,%7}, {%8,%9}, {%0,%1,%2,%3};"
                        : "+f"(c[mi][ni][0]), "+f"(c[mi][ni][1]),
                          "+f"(c[mi][ni][2]), "+f"(c[mi][ni][3])
                        : "r"(a[mi][0]), "r"(a[mi][1]), "r"(a[mi][2]), "r"(a[mi][3]),
                          "r"(b[ni][0]), "r"(b[ni][1]));
                }
        }
        __syncthreads();
    }

    // ---- epilogue: bias + store ----
#pragma unroll
    for (int ni = 0; ni < 8; ni++) {
        int col = n0 + wn + (ni << 3) + (t << 1);
        float2 bv = *(const float2*)(bias + col);
#pragma unroll
        for (int mi = 0; mi < 2; mi++) {
            int row = m0 + wm + (mi << 4) + g;
            float2 v0 = make_float2(c[mi][ni][0] + bv.x, c[mi][ni][1] + bv.y);
            float2 v1 = make_float2(c[mi][ni][2] + bv.x, c[mi][ni][3] + bv.y);
            *(float2*)(C + (size_t)row       * N + col) = v0;
            *(float2*)(C + (size_t)(row + 8) * N + col) = v1;
        }
    }
    (void)ar0;
}

// =============================================================================
// Flash attention (causal), fp32 — unchanged from round 1 except the epilogue
// tf32-rounds the output so the O-projection GEMM needs no in-loop cvt.
// =============================================================================
#define PAD 68

__global__ __launch_bounds__(256) void flash_attn_kernel(
    const float* __restrict__ Q, const float* __restrict__ K,
    const float* __restrict__ V, float* __restrict__ O)
{
    const int qt = blockIdx.x;
    const int h  = blockIdx.y;
    const int b  = blockIdx.z;
    const int tid = threadIdx.x;
    const int tx = tid & 15;
    const int ty = tid >> 4;

    extern __shared__ float sm[];
    float* Qs  = sm;
    float* KPs = sm + 64 * PAD;
    float* Vs  = sm + 2 * 64 * PAD;

    const float* Qb = Q + ((size_t)(b * SS + qt * 64)) * DD + h * DKH;
#pragma unroll
    for (int p = 0; p < 4; p++) {
        int e = p * 256 + tid;
        int r = e >> 4;
        int c = (e & 15) << 2;
        *(float4*)&Qs[r * PAD + c] = *(const float4*)(Qb + (size_t)r * DD + c);
    }

    float m_i[4], l_i[4], o_acc[4][4];
#pragma unroll
    for (int a = 0; a < 4; a++) {
        m_i[a] = -INFINITY;
        l_i[a] = 0.f;
#pragma unroll
        for (int c = 0; c < 4; c++) o_acc[a][c] = 0.f;
    }

    for (int kt = 0; kt <= qt; kt++) {
        __syncthreads();

        const float* Kb = K + ((size_t)(b * SS + kt * 64)) * DD + h * DKH;
        const float* Vb = V + ((size_t)(b * SS + kt * 64)) * DD + h * DKH;
#pragma unroll
        for (int p = 0; p < 4; p++) {
            int e = p * 256 + tid;
            int r = e >> 4;
            int c = (e & 15) << 2;
            *(float4*)&KPs[r * PAD + c] = *(const float4*)(Kb + (size_t)r * DD + c);
            *(float4*)&Vs [r * PAD + c] = *(const float4*)(Vb + (size_t)r * DD + c);
        }
        __syncthreads();

        float s[4][4];
#pragma unroll
        for (int a = 0; a < 4; a++)
#pragma unroll
            for (int c = 0; c < 4; c++) s[a][c] = 0.f;

#pragma unroll
        for (int k4 = 0; k4 < 16; k4++) {
            float4 qa[4], kb[4];
#pragma unroll
            for (int a = 0; a < 4; a++)
                qa[a] = *(float4*)&Qs[(ty * 4 + a) * PAD + k4 * 4];
#pragma unroll
            for (int c = 0; c < 4; c++)
                kb[c] = *(float4*)&KPs[(tx * 4 + c) * PAD + k4 * 4];
#pragma unroll
            for (int a = 0; a < 4; a++)
#pragma unroll
                for (int c = 0; c < 4; c++) {
                    s[a][c] += qa[a].x * kb[c].x;
                    s[a][c] += qa[a].y * kb[c].y;
                    s[a][c] += qa[a].z * kb[c].z;
                    s[a][c] += qa[a].w * kb[c].w;
                }
        }

        const bool diag = (kt == qt);
#pragma unroll
        for (int a = 0; a < 4; a++)
#pragma unroll
            for (int c = 0; c < 4; c++) {
                s[a][c] *= 0.125f;
                if (diag && (tx * 4 + c) > (ty * 4 + a)) s[a][c] = -1e30f;
            }

        float mt[4];
#pragma unroll
        for (int a = 0; a < 4; a++)
            mt[a] = fmaxf(fmaxf(s[a][0], s[a][1]), fmaxf(s[a][2], s[a][3]));
#pragma unroll
        for (int off = 8; off >= 1; off >>= 1)
#pragma unroll
            for (int a = 0; a < 4; a++)
                mt[a] = fmaxf(mt[a], __shfl_xor_sync(0xffffffffu, mt[a], off));

        float alpha[4], rs[4];
#pragma unroll
        for (int a = 0; a < 4; a++) {
            float mn = fmaxf(m_i[a], mt[a]);
            alpha[a] = __expf(m_i[a] - mn);
            m_i[a] = mn;
            rs[a] = 0.f;
#pragma unroll
            for (int c = 0; c < 4; c++) {
                s[a][c] = __expf(s[a][c] - mn);
                rs[a] += s[a][c];
            }
        }
#pragma unroll
        for (int off = 8; off >= 1; off >>= 1)
#pragma unroll
            for (int a = 0; a < 4; a++)
                rs[a] += __shfl_xor_sync(0xffffffffu, rs[a], off);
#pragma unroll
        for (int a = 0; a < 4; a++) {
            l_i[a] = l_i[a] * alpha[a] + rs[a];
#pragma unroll
            for (int c = 0; c < 4; c++) o_acc[a][c] *= alpha[a];
        }

        __syncthreads();
#pragma unroll
        for (int a = 0; a < 4; a++) {
            float4 pv = make_float4(s[a][0], s[a][1], s[a][2], s[a][3]);
            *(float4*)&KPs[(ty * 4 + a) * PAD + tx * 4] = pv;
        }
        __syncthreads();

#pragma unroll
        for (int k4 = 0; k4 < 16; k4++) {
            float4 pa[4];
#pragma unroll
            for (int a = 0; a < 4; a++)
                pa[a] = *(float4*)&KPs[(ty * 4 + a) * PAD + k4 * 4];
#pragma unroll
            for (int u = 0; u < 4; u++) {
                float4 vv = *(float4*)&Vs[(k4 * 4 + u) * PAD + tx * 4];
                float vb[4] = {vv.x, vv.y, vv.z, vv.w};
#pragma unroll
                for (int a = 0; a < 4; a++) {
                    float pv = ((const float*)&pa[a])[u];
#pragma unroll
                    for (int c = 0; c < 4; c++)
                        o_acc[a][c] += pv * vb[c];
                }
            }
        }
    }

#pragma unroll
    for (int a = 0; a < 4; a++) {
        float inv = 1.f / l_i[a];
        int rg = qt * 64 + ty * 4 + a;
        float4 ov = make_float4(tf32r(o_acc[a][0] * inv), tf32r(o_acc[a][1] * inv),
                                tf32r(o_acc[a][2] * inv), tf32r(o_acc[a][3] * inv));
        *(float4*)(O + ((size_t)(b * SS + rg)) * DD + h * DKH + tx * 4) = ov;
    }
}

// =============================================================================
// Launch
// =============================================================================
extern "C" void kernel_launch(void* const* d_in, const int* in_sizes, int n_in,
                              void* d_out, int out_size)
{
    // input order: x, q, k, v, mask, wq, bq, wk, bk, wv, bv, wo, bo
    const float* q  = (const float*)d_in[1];
    const float* k  = (const float*)d_in[2];
    const float* v  = (const float*)d_in[3];
    const float* wq = (const float*)d_in[5];
    const float* bq = (const float*)d_in[6];
    const float* wk = (const float*)d_in[7];
    const float* bk = (const float*)d_in[8];
    const float* wv = (const float*)d_in[9];
    const float* bv = (const float*)d_in[10];
    const float* wo = (const float*)d_in[11];
    const float* bo = (const float*)d_in[12];
    float* out = (float*)d_out;

    float *gq, *gk, *gv, *gao, *tq, *tk, *tv, *wwq, *wwk, *wwv, *wwo;
    cudaGetSymbolAddress((void**)&gq,  g_Q);
    cudaGetSymbolAddress((void**)&gk,  g_K);
    cudaGetSymbolAddress((void**)&gv,  g_V);
    cudaGetSymbolAddress((void**)&gao, g_AO);
    cudaGetSymbolAddress((void**)&tq,  g_Tq);
    cudaGetSymbolAddress((void**)&tk,  g_Tk);
    cudaGetSymbolAddress((void**)&tv,  g_Tv);
    cudaGetSymbolAddress((void**)&wwq, g_Wq);
    cudaGetSymbolAddress((void**)&wwk, g_Wk);
    cudaGetSymbolAddress((void**)&wwv, g_Wv);
    cudaGetSymbolAddress((void**)&wwo, g_Wo);

    const int smem_attn = 3 * 64 * PAD * sizeof(float);
    cudaFuncSetAttribute(flash_attn_kernel,
                         cudaFuncAttributeMaxDynamicSharedMemorySize, smem_attn);

    // ---- tf32 rounding prepass ----
    const int nW4 = DD * DD / 4;
    const int nA4 = MTOT * DD / 4;
    round_tf32_kernel<<<(nW4 + 255) / 256, 256>>>(wq, wwq, nW4);
    round_tf32_kernel<<<(nW4 + 255) / 256, 256>>>(wk, wwk, nW4);
    round_tf32_kernel<<<(nW4 + 255) / 256, 256>>>(wv, wwv, nW4);
    round_tf32_kernel<<<(nW4 + 255) / 256, 256>>>(wo, wwo, nW4);
    round_tf32_kernel<<<(nA4 + 255) / 256, 256>>>(q, tq, nA4);
    round_tf32_kernel<<<(nA4 + 255) / 256, 256>>>(k, tk, nA4);
    round_tf32_kernel<<<(nA4 + 255) / 256, 256>>>(v, tv, nA4);

    dim3 gblk(256);
    dim3 ggrid(DD / 128, MTOT / 128);   // (8, 64)

    gemm_tf32_bias<<<ggrid, gblk>>>(tq, wwq, bq, gq, MTOT, DD, DD);
    gemm_tf32_bias<<<ggrid, gblk>>>(tk, wwk, bk, gk, MTOT, DD, DD);
    gemm_tf32_bias<<<ggrid, gblk>>>(tv, wwv, bv, gv, MTOT, DD, DD);

    dim3 agrid(SS / 64, HH, BB);
    flash_attn_kernel<<<agrid, gblk, smem_attn>>>(gq, gk, gv, gao);

    gemm_tf32_bias<<<ggrid, gblk>>>(gao, wwo, bo, out, MTOT, DD, DD);
}

// round 3
// speedup vs baseline: 3.7088x; 2.4499x over previous
#include <cuda_runtime.h>
#include <math.h>
#include <stdint.h>

// Problem constants
#define BB 4
#define SS 2048
#define DD 1024
#define HH 16
#define DKH 64
#define MTOT (BB*SS)          // 8192 rows

// ---------------- scratch (static device globals; no allocation) -------------
__device__ float g_Q [MTOT*DD];
__device__ float g_K [MTOT*DD];
__device__ float g_V [MTOT*DD];
__device__ float g_AO[MTOT*DD];
__device__ float g_Tq[MTOT*DD];
__device__ float g_Tk[MTOT*DD];
__device__ float g_Tv[MTOT*DD];
__device__ float g_Wq[DD*DD];
__device__ float g_Wk[DD*DD];
__device__ float g_Wv[DD*DD];
__device__ float g_Wo[DD*DD];

// ---------------- tf32 helpers ----------------------------------------------
__device__ __forceinline__ float tf32r(float x) {
    uint32_t u;
    asm("cvt.rna.tf32.f32 %0, %1;" : "=r"(u) : "f"(x));
    return __uint_as_float(u);
}

__global__ __launch_bounds__(256) void round_tf32_kernel(
    const float* __restrict__ in, float* __restrict__ out, int n4)
{
    int i = blockIdx.x * blockDim.x + threadIdx.x;
    if (i < n4) {
        float4 v = ((const float4*)in)[i];
        v.x = tf32r(v.x); v.y = tf32r(v.y);
        v.z = tf32r(v.z); v.w = tf32r(v.w);
        ((float4*)out)[i] = v;
    }
}

// ---------------- cp.async helpers -------------------------------------------
__device__ __forceinline__ void cpa16(uint32_t smem, const void* gmem) {
    asm volatile("cp.async.cg.shared.global [%0], [%1], 16;" :: "r"(smem), "l"(gmem));
}
__device__ __forceinline__ void cpa_commit() {
    asm volatile("cp.async.commit_group;");
}
__device__ __forceinline__ void cpa_wait0() {
    asm volatile("cp.async.wait_group 0;");
}

__device__ __forceinline__ void mma_tf32(
    float c[4], const uint32_t a[4], const uint32_t b[2])
{
    asm volatile(
        "mma.sync.aligned.m16n8k8.row.col.f32.tf32.tf32.f32 "
        "{%0,%1,%2,%3}, {%4,%5,%6,%7}, {%8,%9}, {%0,%1,%2,%3};"
        : "+f"(c[0]), "+f"(c[1]), "+f"(c[2]), "+f"(c[3])
        : "r"(a[0]), "r"(a[1]), "r"(a[2]), "r"(a[3]),
          "r"(b[0]), "r"(b[1]));
}

// =============================================================================
// TF32 tensor-core GEMM with bias (unchanged from round 2)
// =============================================================================
#define APITCH 20
#define BPITCH 136

__global__ __launch_bounds__(256) void gemm_tf32_bias(
    const float* __restrict__ A, const float* __restrict__ W,
    const float* __restrict__ bias, float* __restrict__ C,
    int M, int N, int K)
{
    __shared__ float As[2][128 * APITCH];
    __shared__ float Bs[2][16 * BPITCH];

    const int tid  = threadIdx.x;
    const int wid  = tid >> 5;
    const int lane = tid & 31;
    const int g    = lane >> 2;
    const int t    = lane & 3;
    const int wm   = (wid & 3) << 5;
    const int wn   = (wid >> 2) << 6;
    const int m0   = blockIdx.y << 7;
    const int n0   = blockIdx.x << 7;

    float c[2][8][4];
#pragma unroll
    for (int mi = 0; mi < 2; mi++)
#pragma unroll
        for (int ni = 0; ni < 8; ni++)
#pragma unroll
            for (int j = 0; j < 4; j++) c[mi][ni][j] = 0.f;

    const int NK = K >> 4;

    auto loadTile = [&](int kt, int buf) {
        const int k0 = kt << 4;
#pragma unroll
        for (int i = 0; i < 2; i++) {
            int ca = i * 256 + tid;
            int arr = ca >> 2, ak = (ca & 3) << 2;
            cpa16((uint32_t)__cvta_generic_to_shared(&As[buf][arr * APITCH + ak]),
                  A + (size_t)(m0 + arr) * K + k0 + ak);
            int brr = ca >> 5, bn = (ca & 31) << 2;
            cpa16((uint32_t)__cvta_generic_to_shared(&Bs[buf][brr * BPITCH + bn]),
                  W + (size_t)(k0 + brr) * N + n0 + bn);
        }
        cpa_commit();
    };

    loadTile(0, 0);

    for (int kt = 0; kt < NK; kt++) {
        const int buf = kt & 1;
        cpa_wait0();
        __syncthreads();
        if (kt + 1 < NK) loadTile(kt + 1, buf ^ 1);

        const float* as = As[buf];
        const float* bs = Bs[buf];

#pragma unroll
        for (int ks = 0; ks < 16; ks += 8) {
            uint32_t a[2][4], b[8][2];
#pragma unroll
            for (int mi = 0; mi < 2; mi++) {
                int mr = wm + (mi << 4) + g;
                a[mi][0] = __float_as_uint(as[(mr    ) * APITCH + ks + t    ]);
                a[mi][1] = __float_as_uint(as[(mr + 8) * APITCH + ks + t    ]);
                a[mi][2] = __float_as_uint(as[(mr    ) * APITCH + ks + t + 4]);
                a[mi][3] = __float_as_uint(as[(mr + 8) * APITCH + ks + t + 4]);
            }
#pragma unroll
            for (int ni = 0; ni < 8; ni++) {
                int nc = wn + (ni << 3) + g;
                b[ni][0] = __float_as_uint(bs[(ks + t    ) * BPITCH + nc]);
                b[ni][1] = __float_as_uint(bs[(ks + t + 4) * BPITCH + nc]);
            }
#pragma unroll
            for (int mi = 0; mi < 2; mi++)
#pragma unroll
                for (int ni = 0; ni < 8; ni++)
                    mma_tf32(c[mi][ni], a[mi], b[ni]);
        }
        __syncthreads();
    }

#pragma unroll
    for (int ni = 0; ni < 8; ni++) {
        int col = n0 + wn + (ni << 3) + (t << 1);
        float2 bv = *(const float2*)(bias + col);
#pragma unroll
        for (int mi = 0; mi < 2; mi++) {
            int row = m0 + wm + (mi << 4) + g;
            float2 v0 = make_float2(c[mi][ni][0] + bv.x, c[mi][ni][1] + bv.y);
            float2 v1 = make_float2(c[mi][ni][2] + bv.x, c[mi][ni][3] + bv.y);
            *(float2*)(C + (size_t)row       * N + col) = v0;
            *(float2*)(C + (size_t)(row + 8) * N + col) = v1;
        }
    }
}

// =============================================================================
// TF32 tensor-core flash attention (causal).
// Grid: (S/128, H, B), block 128 threads (4 warps), warp tile 32 rows.
// Br=128, Bc=64, DK=64. mma.m16n8k8.tf32 for S=QK^T and O+=P*V.
// Smem pitches: Q/K/P pitch 68 (lane addr = 4g+t, conflict-free),
// V pitch 72 (lane addr = 8t+g, conflict-free).
// =============================================================================
#define FPAD 68
#define VPAD 72
#define ATT_SMEM ((128*FPAD + 64*FPAD + 64*VPAD + 128*FPAD) * 4)

__global__ __launch_bounds__(128) void flash_mma_kernel(
    const float* __restrict__ Q, const float* __restrict__ K,
    const float* __restrict__ V, float* __restrict__ O)
{
    const int qt = (SS / 128 - 1) - blockIdx.x;   // heavy blocks first
    const int h  = blockIdx.y;
    const int b  = blockIdx.z;
    const int tid  = threadIdx.x;
    const int warp = tid >> 5;
    const int lane = tid & 31;
    const int g    = lane >> 2;
    const int t    = lane & 3;
    const int wm   = warp << 5;      // warp row offset (32 rows per warp)

    extern __shared__ float sm[];
    float* Qs = sm;                       // [128][FPAD]
    float* Ks = Qs + 128 * FPAD;          // [64][FPAD]
    float* Vs = Ks + 64 * FPAD;           // [64][VPAD]
    float* Ps = Vs + 64 * VPAD;           // [128][FPAD]

    // ---- load Q tile (128 x 64), tf32-rounded ----
    const float* Qb = Q + ((size_t)(b * SS + qt * 128)) * DD + h * DKH;
#pragma unroll
    for (int i = 0; i < 16; i++) {
        int e = i * 128 + tid;           // float4 index
        int r = e >> 4;
        int c = (e & 15) << 2;
        float4 v = *(const float4*)(Qb + (size_t)r * DD + c);
        Qs[r * FPAD + c + 0] = tf32r(v.x);
        Qs[r * FPAD + c + 1] = tf32r(v.y);
        Qs[r * FPAD + c + 2] = tf32r(v.z);
        Qs[r * FPAD + c + 3] = tf32r(v.w);
    }

    float m_i[2][2], l_i[2][2], co[2][8][4];
#pragma unroll
    for (int mi = 0; mi < 2; mi++)
#pragma unroll
        for (int hh = 0; hh < 2; hh++) { m_i[mi][hh] = -INFINITY; l_i[mi][hh] = 0.f; }
#pragma unroll
    for (int mi = 0; mi < 2; mi++)
#pragma unroll
        for (int ni = 0; ni < 8; ni++)
#pragma unroll
            for (int j = 0; j < 4; j++) co[mi][ni][j] = 0.f;

    const int ktmax = 2 * qt + 1;

    for (int kt = 0; kt <= ktmax; kt++) {
        __syncthreads();   // previous iter's K/V reads complete (and Q stores, iter 0)

        // ---- load K,V tiles (64 x 64 each), tf32-rounded ----
        const float* Kb = K + ((size_t)(b * SS + kt * 64)) * DD + h * DKH;
        const float* Vb = V + ((size_t)(b * SS + kt * 64)) * DD + h * DKH;
#pragma unroll
        for (int i = 0; i < 8; i++) {
            int e = i * 128 + tid;
            int r = e >> 4;
            int c = (e & 15) << 2;
            float4 kv = *(const float4*)(Kb + (size_t)r * DD + c);
            Ks[r * FPAD + c + 0] = tf32r(kv.x);
            Ks[r * FPAD + c + 1] = tf32r(kv.y);
            Ks[r * FPAD + c + 2] = tf32r(kv.z);
            Ks[r * FPAD + c + 3] = tf32r(kv.w);
            float4 vv = *(const float4*)(Vb + (size_t)r * DD + c);
            Vs[r * VPAD + c + 0] = tf32r(vv.x);
            Vs[r * VPAD + c + 1] = tf32r(vv.y);
            Vs[r * VPAD + c + 2] = tf32r(vv.z);
            Vs[r * VPAD + c + 3] = tf32r(vv.w);
        }
        __syncthreads();

        // ---- S = Q K^T ----
        float cs[2][8][4];
#pragma unroll
        for (int mi = 0; mi < 2; mi++)
#pragma unroll
            for (int ni = 0; ni < 8; ni++)
#pragma unroll
                for (int j = 0; j < 4; j++) cs[mi][ni][j] = 0.f;

#pragma unroll
        for (int ks = 0; ks < 8; ks++) {
            uint32_t a[2][4], bf[8][2];
#pragma unroll
            for (int mi = 0; mi < 2; mi++) {
                int row = wm + (mi << 4) + g;
                a[mi][0] = __float_as_uint(Qs[(row    ) * FPAD + (ks << 3) + t    ]);
                a[mi][1] = __float_as_uint(Qs[(row + 8) * FPAD + (ks << 3) + t    ]);
                a[mi][2] = __float_as_uint(Qs[(row    ) * FPAD + (ks << 3) + t + 4]);
                a[mi][3] = __float_as_uint(Qs[(row + 8) * FPAD + (ks << 3) + t + 4]);
            }
#pragma unroll
            for (int ni = 0; ni < 8; ni++) {
                int key = (ni << 3) + g;
                bf[ni][0] = __float_as_uint(Ks[key * FPAD + (ks << 3) + t    ]);
                bf[ni][1] = __float_as_uint(Ks[key * FPAD + (ks << 3) + t + 4]);
            }
#pragma unroll
            for (int mi = 0; mi < 2; mi++)
#pragma unroll
                for (int ni = 0; ni < 8; ni++)
                    mma_tf32(cs[mi][ni], a[mi], bf[ni]);
        }

        // ---- scale + causal mask ----
        const bool need_mask = (kt >= 2 * qt);
#pragma unroll
        for (int mi = 0; mi < 2; mi++)
#pragma unroll
            for (int ni = 0; ni < 8; ni++)
#pragma unroll
                for (int j = 0; j < 4; j++) {
                    float s = cs[mi][ni][j] * 0.125f;
                    if (need_mask) {
                        int row = qt * 128 + wm + (mi << 4) + g + ((j >> 1) << 3);
                        int col = kt * 64 + (ni << 3) + (t << 1) + (j & 1);
                        if (col > row) s = -1e9f;
                    }
                    cs[mi][ni][j] = s;
                }

        // ---- row max (reduce across 4 t-lanes) ----
        float mt[2][2];
#pragma unroll
        for (int mi = 0; mi < 2; mi++)
#pragma unroll
            for (int hh = 0; hh < 2; hh++) {
                float mx = -INFINITY;
#pragma unroll
                for (int ni = 0; ni < 8; ni++)
                    mx = fmaxf(mx, fmaxf(cs[mi][ni][2*hh], cs[mi][ni][2*hh+1]));
                mx = fmaxf(mx, __shfl_xor_sync(0xffffffffu, mx, 1));
                mx = fmaxf(mx, __shfl_xor_sync(0xffffffffu, mx, 2));
                mt[mi][hh] = mx;
            }

        // ---- online softmax update ----
        float al[2][2], mn[2][2];
#pragma unroll
        for (int mi = 0; mi < 2; mi++)
#pragma unroll
            for (int hh = 0; hh < 2; hh++) {
                float m2 = fmaxf(m_i[mi][hh], mt[mi][hh]);
                al[mi][hh] = __expf(m_i[mi][hh] - m2);
                m_i[mi][hh] = m2;
                mn[mi][hh] = m2;
            }

        float rs[2][2] = {{0.f,0.f},{0.f,0.f}};
#pragma unroll
        for (int mi = 0; mi < 2; mi++)
#pragma unroll
            for (int ni = 0; ni < 8; ni++)
#pragma unroll
                for (int j = 0; j < 4; j++) {
                    int hh = j >> 1;
                    float e = __expf(cs[mi][ni][j] - mn[mi][hh]);
                    cs[mi][ni][j] = e;
                    rs[mi][hh] += e;
                }
#pragma unroll
        for (int mi = 0; mi < 2; mi++)
#pragma unroll
            for (int hh = 0; hh < 2; hh++) {
                float r = rs[mi][hh];
                r += __shfl_xor_sync(0xffffffffu, r, 1);
                r += __shfl_xor_sync(0xffffffffu, r, 2);
                l_i[mi][hh] = l_i[mi][hh] * al[mi][hh] + r;
            }
#pragma unroll
        for (int mi = 0; mi < 2; mi++)
#pragma unroll
            for (int ni = 0; ni < 8; ni++)
#pragma unroll
                for (int j = 0; j < 4; j++)
                    co[mi][ni][j] *= al[mi][j >> 1];

        // ---- store P (tf32) to warp-private smem rows ----
#pragma unroll
        for (int mi = 0; mi < 2; mi++) {
            int row = wm + (mi << 4) + g;
#pragma unroll
            for (int ni = 0; ni < 8; ni++) {
                int col = (ni << 3) + (t << 1);
                float2 p0 = make_float2(tf32r(cs[mi][ni][0]), tf32r(cs[mi][ni][1]));
                float2 p1 = make_float2(tf32r(cs[mi][ni][2]), tf32r(cs[mi][ni][3]));
                *(float2*)&Ps[(row    ) * FPAD + col] = p0;
                *(float2*)&Ps[(row + 8) * FPAD + col] = p1;
            }
        }
        __syncwarp();

        // ---- O += P @ V ----
#pragma unroll
        for (int ks = 0; ks < 8; ks++) {
            uint32_t a[2][4], bf[8][2];
#pragma unroll
            for (int mi = 0; mi < 2; mi++) {
                int row = wm + (mi << 4) + g;
                a[mi][0] = __float_as_uint(Ps[(row    ) * FPAD + (ks << 3) + t    ]);
                a[mi][1] = __float_as_uint(Ps[(row + 8) * FPAD + (ks << 3) + t    ]);
                a[mi][2] = __float_as_uint(Ps[(row    ) * FPAD + (ks << 3) + t + 4]);
                a[mi][3] = __float_as_uint(Ps[(row + 8) * FPAD + (ks << 3) + t + 4]);
            }
#pragma unroll
            for (int ni = 0; ni < 8; ni++) {
                bf[ni][0] = __float_as_uint(Vs[((ks << 3) + t    ) * VPAD + (ni << 3) + g]);
                bf[ni][1] = __float_as_uint(Vs[((ks << 3) + t + 4) * VPAD + (ni << 3) + g]);
            }
#pragma unroll
            for (int mi = 0; mi < 2; mi++)
#pragma unroll
                for (int ni = 0; ni < 8; ni++)
                    mma_tf32(co[mi][ni], a[mi], bf[ni]);
        }
    }

    // ---- epilogue: normalize, tf32-round, store ----
#pragma unroll
    for (int mi = 0; mi < 2; mi++)
#pragma unroll
        for (int hh = 0; hh < 2; hh++) {
            float inv = 1.f / l_i[mi][hh];
            int row = qt * 128 + wm + (mi << 4) + g + (hh << 3);
            float* ob = O + ((size_t)(b * SS + row)) * DD + h * DKH;
#pragma unroll
            for (int ni = 0; ni < 8; ni++) {
                int col = (ni << 3) + (t << 1);
                float2 v = make_float2(tf32r(co[mi][ni][2*hh]   * inv),
                                       tf32r(co[mi][ni][2*hh+1] * inv));
                *(float2*)(ob + col) = v;
            }
        }
}

// =============================================================================
// Launch
// =============================================================================
extern "C" void kernel_launch(void* const* d_in, const int* in_sizes, int n_in,
                              void* d_out, int out_size)
{
    // input order: x, q, k, v, mask, wq, bq, wk, bk, wv, bv, wo, bo
    const float* q  = (const float*)d_in[1];
    const float* k  = (const float*)d_in[2];
    const float* v  = (const float*)d_in[3];
    const float* wq = (const float*)d_in[5];
    const float* bq = (const float*)d_in[6];
    const float* wk = (const float*)d_in[7];
    const float* bk = (const float*)d_in[8];
    const float* wv = (const float*)d_in[9];
    const float* bv = (const float*)d_in[10];
    const float* wo = (const float*)d_in[11];
    const float* bo = (const float*)d_in[12];
    float* out = (float*)d_out;

    float *gq, *gk, *gv, *gao, *tq, *tk, *tv, *wwq, *wwk, *wwv, *wwo;
    cudaGetSymbolAddress((void**)&gq,  g_Q);
    cudaGetSymbolAddress((void**)&gk,  g_K);
    cudaGetSymbolAddress((void**)&gv,  g_V);
    cudaGetSymbolAddress((void**)&gao, g_AO);
    cudaGetSymbolAddress((void**)&tq,  g_Tq);
    cudaGetSymbolAddress((void**)&tk,  g_Tk);
    cudaGetSymbolAddress((void**)&tv,  g_Tv);
    cudaGetSymbolAddress((void**)&wwq, g_Wq);
    cudaGetSymbolAddress((void**)&wwk, g_Wk);
    cudaGetSymbolAddress((void**)&wwv, g_Wv);
    cudaGetSymbolAddress((void**)&wwo, g_Wo);

    cudaFuncSetAttribute(flash_mma_kernel,
                         cudaFuncAttributeMaxDynamicSharedMemorySize, ATT_SMEM);

    // ---- tf32 rounding prepass ----
    const int nW4 = DD * DD / 4;
    const int nA4 = MTOT * DD / 4;
    round_tf32_kernel<<<(nW4 + 255) / 256, 256>>>(wq, wwq, nW4);
    round_tf32_kernel<<<(nW4 + 255) / 256, 256>>>(wk, wwk, nW4);
    round_tf32_kernel<<<(nW4 + 255) / 256, 256>>>(wv, wwv, nW4);
    round_tf32_kernel<<<(nW4 + 255) / 256, 256>>>(wo, wwo, nW4);
    round_tf32_kernel<<<(nA4 + 255) / 256, 256>>>(q, tq, nA4);
    round_tf32_kernel<<<(nA4 + 255) / 256, 256>>>(k, tk, nA4);
    round_tf32_kernel<<<(nA4 + 255) / 256, 256>>>(v, tv, nA4);

    dim3 gblk(256);
    dim3 ggrid(DD / 128, MTOT / 128);   // (8, 64)

    gemm_tf32_bias<<<ggrid, gblk>>>(tq, wwq, bq, gq, MTOT, DD, DD);
    gemm_tf32_bias<<<ggrid, gblk>>>(tk, wwk, bk, gk, MTOT, DD, DD);
    gemm_tf32_bias<<<ggrid, gblk>>>(tv, wwv, bv, gv, MTOT, DD, DD);

    dim3 agrid(SS / 128, HH, BB);       // (16, 16, 4)
    flash_mma_kernel<<<agrid, dim3(128), ATT_SMEM>>>(gq, gk, gv, gao);

    gemm_tf32_bias<<<ggrid, gblk>>>(gao, wwo, bo, out, MTOT, DD, DD);
}

// round 5
// speedup vs baseline: 3.9042x; 1.0527x over previous
#include <cuda_runtime.h>
#include <math.h>
#include <stdint.h>

// Problem constants
#define BB 4
#define SS 2048
#define DD 1024
#define HH 16
#define DKH 64
#define MTOT (BB*SS)          // 8192 rows

// ---------------- scratch (static device globals; no allocation) -------------
__device__ float g_Q [MTOT*DD];
__device__ float g_K [MTOT*DD];
__device__ float g_V [MTOT*DD];
__device__ float g_AO[MTOT*DD];
__device__ float g_Wq[DD*DD];   // tf32-rounded weights, original [K][N] layout
__device__ float g_Wk[DD*DD];
__device__ float g_Wv[DD*DD];
__device__ float g_Wo[DD*DD];

// ---------------- helpers -----------------------------------------------------
__device__ __forceinline__ float tf32r(float x) {
    uint32_t u;
    asm("cvt.rna.tf32.f32 %0, %1;" : "=r"(u) : "f"(x));
    return __uint_as_float(u);
}
__device__ __forceinline__ uint32_t tf32u(float x) {
    uint32_t u;
    asm("cvt.rna.tf32.f32 %0, %1;" : "=r"(u) : "f"(x));
    return u;
}
__device__ __forceinline__ void cpa16(uint32_t smem, const void* gmem) {
    asm volatile("cp.async.cg.shared.global [%0], [%1], 16;" :: "r"(smem), "l"(gmem));
}
__device__ __forceinline__ void cpa_commit() {
    asm volatile("cp.async.commit_group;");
}
template<int N> __device__ __forceinline__ void cpa_wait() {
    asm volatile("cp.async.wait_group %0;" :: "n"(N));
}
__device__ __forceinline__ uint32_t smem_u32(const void* p) {
    uint32_t a;
    asm("{ .reg .u64 t; cvta.to.shared.u64 t, %1; cvt.u32.u64 %0, t; }"
        : "=r"(a) : "l"(p));
    return a;
}
__device__ __forceinline__ void mma_tf32(
    float c[4], const uint32_t a[4], const uint32_t b[2])
{
    asm volatile(
        "mma.sync.aligned.m16n8k8.row.col.f32.tf32.tf32.f32 "
        "{%0,%1,%2,%3}, {%4,%5,%6,%7}, {%8,%9}, {%0,%1,%2,%3};"
        : "+f"(c[0]), "+f"(c[1]), "+f"(c[2]), "+f"(c[3])
        : "r"(a[0]), "r"(a[1]), "r"(a[2]), "r"(a[3]),
          "r"(b[0]), "r"(b[1]));
}

// ---------------- weight rounding prepass ------------------------------------
__global__ __launch_bounds__(256) void round_tf32_kernel(
    const float* __restrict__ in, float* __restrict__ out, int n4)
{
    int i = blockIdx.x * blockDim.x + threadIdx.x;
    if (i < n4) {
        float4 v = ((const float4*)in)[i];
        v.x = tf32r(v.x); v.y = tf32r(v.y);
        v.z = tf32r(v.z); v.w = tf32r(v.w);
        ((float4*)out)[i] = v;
    }
}

// =============================================================================
// TF32 HMMA GEMM v2: C[M,N] = A[M,K] @ W[K,N] + bias[N]
// Block tile 128x128, K-tile 32, 256 threads (8 warps, warp tile 32x64),
// 3-stage cp.async ring, ONE __syncthreads per K-iteration.
// A rounded to tf32 in-register at fragment load (idempotent); W pre-rounded.
// Smem: A [128][36] floats + B [32][136] floats per stage; 3 stages = 107520 B.
// Fragment LDS conflict-free: A lane addr = 4g+t, B lane addr = 8t+g (mod 32).
// =============================================================================
#define GAP 36
#define GBP 136
#define G_ASZ (128 * GAP)          // floats per A stage
#define G_BSZ (32 * GBP)           // floats per B stage
#define G_STG (G_ASZ + G_BSZ)
#define G_SMEM (3 * G_STG * 4)     // 107520 bytes
#define GNT (DD / 32)              // 32 K-iterations

__global__ __launch_bounds__(256) void gemm_hmma(
    const float* __restrict__ A, const float* __restrict__ W,
    const float* __restrict__ bias, float* __restrict__ C,
    int M, int N, int K)
{
    extern __shared__ float sh[];

    const int tid  = threadIdx.x;
    const int wid  = tid >> 5;
    const int lane = tid & 31;
    const int g    = lane >> 2;
    const int t    = lane & 3;
    const int wm   = (wid & 3) << 5;   // 0,32,64,96
    const int wn   = (wid >> 2) << 6;  // 0,64
    const int m0   = blockIdx.y << 7;
    const int n0   = blockIdx.x << 7;

    float c[2][8][4];
#pragma unroll
    for (int mi = 0; mi < 2; mi++)
#pragma unroll
        for (int ni = 0; ni < 8; ni++)
#pragma unroll
            for (int j = 0; j < 4; j++) c[mi][ni][j] = 0.f;

    // per-thread load coordinates (4 float4 chunks for A, 4 for B per tile)
    // A chunk c = j*256+tid : row=c>>3 (0..127), k4=c&7
    // B chunk c = j*256+tid : row=c>>5 (0..31),  n4=c&31
    const uint32_t shbase = smem_u32(sh);

    auto load_tile = [&](int kt, int stg) {
        const int k0 = kt << 5;
        const uint32_t sa = shbase + (stg * G_STG) * 4;
        const uint32_t sb = sa + G_ASZ * 4;
#pragma unroll
        for (int j = 0; j < 4; j++) {
            int ca = j * 256 + tid;
            int row = ca >> 3, k4 = ca & 7;
            cpa16(sa + (row * GAP + (k4 << 2)) * 4,
                  A + (size_t)(m0 + row) * K + k0 + (k4 << 2));
        }
#pragma unroll
        for (int j = 0; j < 4; j++) {
            int cb = j * 256 + tid;
            int row = cb >> 5, n4 = cb & 31;
            cpa16(sb + (row * GBP + (n4 << 2)) * 4,
                  W + (size_t)(k0 + row) * N + n0 + (n4 << 2));
        }
        cpa_commit();
    };

    load_tile(0, 0);
    load_tile(1, 1);

    for (int kt = 0; kt < GNT; kt++) {
        if (kt + 1 < GNT) cpa_wait<1>(); else cpa_wait<0>();
        __syncthreads();
        if (kt + 2 < GNT) load_tile(kt + 2, (kt + 2) % 3);

        const int stg = kt % 3;
        const float* as = sh + stg * G_STG;
        const float* bs = as + G_ASZ;

#pragma unroll
        for (int ks = 0; ks < 32; ks += 8) {
            uint32_t a[2][4], b[8][2];
#pragma unroll
            for (int mi = 0; mi < 2; mi++) {
                int mr = wm + (mi << 4) + g;
                a[mi][0] = tf32u(as[(mr    ) * GAP + ks + t    ]);
                a[mi][1] = tf32u(as[(mr + 8) * GAP + ks + t    ]);
                a[mi][2] = tf32u(as[(mr    ) * GAP + ks + t + 4]);
                a[mi][3] = tf32u(as[(mr + 8) * GAP + ks + t + 4]);
            }
#pragma unroll
            for (int ni = 0; ni < 8; ni++) {
                int nc = wn + (ni << 3) + g;
                b[ni][0] = __float_as_uint(bs[(ks + t    ) * GBP + nc]);
                b[ni][1] = __float_as_uint(bs[(ks + t + 4) * GBP + nc]);
            }
#pragma unroll
            for (int mi = 0; mi < 2; mi++)
#pragma unroll
                for (int ni = 0; ni < 8; ni++)
                    mma_tf32(c[mi][ni], a[mi], b[ni]);
        }
    }

    // ---- epilogue: bias + store ----
#pragma unroll
    for (int ni = 0; ni < 8; ni++) {
        int col = n0 + wn + (ni << 3) + (t << 1);
        float2 bv = *(const float2*)(bias + col);
#pragma unroll
        for (int mi = 0; mi < 2; mi++) {
            int row = m0 + wm + (mi << 4) + g;
            float2 v0 = make_float2(c[mi][ni][0] + bv.x, c[mi][ni][1] + bv.y);
            float2 v1 = make_float2(c[mi][ni][2] + bv.x, c[mi][ni][3] + bv.y);
            *(float2*)(C + (size_t)row       * N + col) = v0;
            *(float2*)(C + (size_t)(row + 8) * N + col) = v1;
        }
    }
}

// =============================================================================
// TF32 tensor-core flash attention (causal) — unchanged from round 3.
// =============================================================================
#define FPAD 68
#define VPAD 72
#define ATT_SMEM ((128*FPAD + 64*FPAD + 64*VPAD + 128*FPAD) * 4)

__global__ __launch_bounds__(128) void flash_mma_kernel(
    const float* __restrict__ Q, const float* __restrict__ K,
    const float* __restrict__ V, float* __restrict__ O)
{
    const int qt = (SS / 128 - 1) - blockIdx.x;
    const int h  = blockIdx.y;
    const int b  = blockIdx.z;
    const int tid  = threadIdx.x;
    const int warp = tid >> 5;
    const int lane = tid & 31;
    const int g    = lane >> 2;
    const int t    = lane & 3;
    const int wm   = warp << 5;

    extern __shared__ float sm[];
    float* Qs = sm;
    float* Ks = Qs + 128 * FPAD;
    float* Vs = Ks + 64 * FPAD;
    float* Ps = Vs + 64 * VPAD;

    const float* Qb = Q + ((size_t)(b * SS + qt * 128)) * DD + h * DKH;
#pragma unroll
    for (int i = 0; i < 16; i++) {
        int e = i * 128 + tid;
        int r = e >> 4;
        int c = (e & 15) << 2;
        float4 v = *(const float4*)(Qb + (size_t)r * DD + c);
        Qs[r * FPAD + c + 0] = tf32r(v.x);
        Qs[r * FPAD + c + 1] = tf32r(v.y);
        Qs[r * FPAD + c + 2] = tf32r(v.z);
        Qs[r * FPAD + c + 3] = tf32r(v.w);
    }

    float m_i[2][2], l_i[2][2], co[2][8][4];
#pragma unroll
    for (int mi = 0; mi < 2; mi++)
#pragma unroll
        for (int hh = 0; hh < 2; hh++) { m_i[mi][hh] = -INFINITY; l_i[mi][hh] = 0.f; }
#pragma unroll
    for (int mi = 0; mi < 2; mi++)
#pragma unroll
        for (int ni = 0; ni < 8; ni++)
#pragma unroll
            for (int j = 0; j < 4; j++) co[mi][ni][j] = 0.f;

    const int ktmax = 2 * qt + 1;

    for (int kt = 0; kt <= ktmax; kt++) {
        __syncthreads();

        const float* Kb = K + ((size_t)(b * SS + kt * 64)) * DD + h * DKH;
        const float* Vb = V + ((size_t)(b * SS + kt * 64)) * DD + h * DKH;
#pragma unroll
        for (int i = 0; i < 8; i++) {
            int e = i * 128 + tid;
            int r = e >> 4;
            int c = (e & 15) << 2;
            float4 kv = *(const float4*)(Kb + (size_t)r * DD + c);
            Ks[r * FPAD + c + 0] = tf32r(kv.x);
            Ks[r * FPAD + c + 1] = tf32r(kv.y);
            Ks[r * FPAD + c + 2] = tf32r(kv.z);
            Ks[r * FPAD + c + 3] = tf32r(kv.w);
            float4 vv = *(const float4*)(Vb + (size_t)r * DD + c);
            Vs[r * VPAD + c + 0] = tf32r(vv.x);
            Vs[r * VPAD + c + 1] = tf32r(vv.y);
            Vs[r * VPAD + c + 2] = tf32r(vv.z);
            Vs[r * VPAD + c + 3] = tf32r(vv.w);
        }
        __syncthreads();

        float cs[2][8][4];
#pragma unroll
        for (int mi = 0; mi < 2; mi++)
#pragma unroll
            for (int ni = 0; ni < 8; ni++)
#pragma unroll
                for (int j = 0; j < 4; j++) cs[mi][ni][j] = 0.f;

#pragma unroll
        for (int ks = 0; ks < 8; ks++) {
            uint32_t a[2][4], bf[8][2];
#pragma unroll
            for (int mi = 0; mi < 2; mi++) {
                int row = wm + (mi << 4) + g;
                a[mi][0] = __float_as_uint(Qs[(row    ) * FPAD + (ks << 3) + t    ]);
                a[mi][1] = __float_as_uint(Qs[(row + 8) * FPAD + (ks << 3) + t    ]);
                a[mi][2] = __float_as_uint(Qs[(row    ) * FPAD + (ks << 3) + t + 4]);
                a[mi][3] = __float_as_uint(Qs[(row + 8) * FPAD + (ks << 3) + t + 4]);
            }
#pragma unroll
            for (int ni = 0; ni < 8; ni++) {
                int key = (ni << 3) + g;
                bf[ni][0] = __float_as_uint(Ks[key * FPAD + (ks << 3) + t    ]);
                bf[ni][1] = __float_as_uint(Ks[key * FPAD + (ks << 3) + t + 4]);
            }
#pragma unroll
            for (int mi = 0; mi < 2; mi++)
#pragma unroll
                for (int ni = 0; ni < 8; ni++)
                    mma_tf32(cs[mi][ni], a[mi], bf[ni]);
        }

        const bool need_mask = (kt >= 2 * qt);
#pragma unroll
        for (int mi = 0; mi < 2; mi++)
#pragma unroll
            for (int ni = 0; ni < 8; ni++)
#pragma unroll
                for (int j = 0; j < 4; j++) {
                    float s = cs[mi][ni][j] * 0.125f;
                    if (need_mask) {
                        int row = qt * 128 + wm + (mi << 4) + g + ((j >> 1) << 3);
                        int col = kt * 64 + (ni << 3) + (t << 1) + (j & 1);
                        if (col > row) s = -1e9f;
                    }
                    cs[mi][ni][j] = s;
                }

        float mt[2][2];
#pragma unroll
        for (int mi = 0; mi < 2; mi++)
#pragma unroll
            for (int hh = 0; hh < 2; hh++) {
                float mx = -INFINITY;
#pragma unroll
                for (int ni = 0; ni < 8; ni++)
                    mx = fmaxf(mx, fmaxf(cs[mi][ni][2*hh], cs[mi][ni][2*hh+1]));
                mx = fmaxf(mx, __shfl_xor_sync(0xffffffffu, mx, 1));
                mx = fmaxf(mx, __shfl_xor_sync(0xffffffffu, mx, 2));
                mt[mi][hh] = mx;
            }

        float al[2][2], mn[2][2];
#pragma unroll
        for (int mi = 0; mi < 2; mi++)
#pragma unroll
            for (int hh = 0; hh < 2; hh++) {
                float m2 = fmaxf(m_i[mi][hh], mt[mi][hh]);
                al[mi][hh] = __expf(m_i[mi][hh] - m2);
                m_i[mi][hh] = m2;
                mn[mi][hh] = m2;
            }

        float rs[2][2] = {{0.f,0.f},{0.f,0.f}};
#pragma unroll
        for (int mi = 0; mi < 2; mi++)
#pragma unroll
            for (int ni = 0; ni < 8; ni++)
#pragma unroll
                for (int j = 0; j < 4; j++) {
                    int hh = j >> 1;
                    float e = __expf(cs[mi][ni][j] - mn[mi][hh]);
                    cs[mi][ni][j] = e;
                    rs[mi][hh] += e;
                }
#pragma unroll
        for (int mi = 0; mi < 2; mi++)
#pragma unroll
            for (int hh = 0; hh < 2; hh++) {
                float r = rs[mi][hh];
                r += __shfl_xor_sync(0xffffffffu, r, 1);
                r += __shfl_xor_sync(0xffffffffu, r, 2);
                l_i[mi][hh] = l_i[mi][hh] * al[mi][hh] + r;
            }
#pragma unroll
        for (int mi = 0; mi < 2; mi++)
#pragma unroll
            for (int ni = 0; ni < 8; ni++)
#pragma unroll
                for (int j = 0; j < 4; j++)
                    co[mi][ni][j] *= al[mi][j >> 1];

#pragma unroll
        for (int mi = 0; mi < 2; mi++) {
            int row = wm + (mi << 4) + g;
#pragma unroll
            for (int ni = 0; ni < 8; ni++) {
                int col = (ni << 3) + (t << 1);
                float2 p0 = make_float2(tf32r(cs[mi][ni][0]), tf32r(cs[mi][ni][1]));
                float2 p1 = make_float2(tf32r(cs[mi][ni][2]), tf32r(cs[mi][ni][3]));
                *(float2*)&Ps[(row    ) * FPAD + col] = p0;
                *(float2*)&Ps[(row + 8) * FPAD + col] = p1;
            }
        }
        __syncwarp();

#pragma unroll
        for (int ks = 0; ks < 8; ks++) {
            uint32_t a[2][4], bf[8][2];
#pragma unroll
            for (int mi = 0; mi < 2; mi++) {
                int row = wm + (mi << 4) + g;
                a[mi][0] = __float_as_uint(Ps[(row    ) * FPAD + (ks << 3) + t    ]);
                a[mi][1] = __float_as_uint(Ps[(row + 8) * FPAD + (ks << 3) + t    ]);
                a[mi][2] = __float_as_uint(Ps[(row    ) * FPAD + (ks << 3) + t + 4]);
                a[mi][3] = __float_as_uint(Ps[(row + 8) * FPAD + (ks << 3) + t + 4]);
            }
#pragma unroll
            for (int ni = 0; ni < 8; ni++) {
                bf[ni][0] = __float_as_uint(Vs[((ks << 3) + t    ) * VPAD + (ni << 3) + g]);
                bf[ni][1] = __float_as_uint(Vs[((ks << 3) + t + 4) * VPAD + (ni << 3) + g]);
            }
#pragma unroll
            for (int mi = 0; mi < 2; mi++)
#pragma unroll
                for (int ni = 0; ni < 8; ni++)
                    mma_tf32(co[mi][ni], a[mi], bf[ni]);
        }
    }

#pragma unroll
    for (int mi = 0; mi < 2; mi++)
#pragma unroll
        for (int hh = 0; hh < 2; hh++) {
            float inv = 1.f / l_i[mi][hh];
            int row = qt * 128 + wm + (mi << 4) + g + (hh << 3);
            float* ob = O + ((size_t)(b * SS + row)) * DD + h * DKH;
#pragma unroll
            for (int ni = 0; ni < 8; ni++) {
                int col = (ni << 3) + (t << 1);
                float2 v = make_float2(tf32r(co[mi][ni][2*hh]   * inv),
                                       tf32r(co[mi][ni][2*hh+1] * inv));
                *(float2*)(ob + col) = v;
            }
        }
}

// =============================================================================
// Launch
// =============================================================================
extern "C" void kernel_launch(void* const* d_in, const int* in_sizes, int n_in,
                              void* d_out, int out_size)
{
    // input order: x, q, k, v, mask, wq, bq, wk, bk, wv, bv, wo, bo
    const float* q  = (const float*)d_in[1];
    const float* k  = (const float*)d_in[2];
    const float* v  = (const float*)d_in[3];
    const float* wq = (const float*)d_in[5];
    const float* bq = (const float*)d_in[6];
    const float* wk = (const float*)d_in[7];
    const float* bk = (const float*)d_in[8];
    const float* wv = (const float*)d_in[9];
    const float* bv = (const float*)d_in[10];
    const float* wo = (const float*)d_in[11];
    const float* bo = (const float*)d_in[12];
    float* out = (float*)d_out;

    float *gq, *gk, *gv, *gao, *wwq, *wwk, *wwv, *wwo;
    cudaGetSymbolAddress((void**)&gq,  g_Q);
    cudaGetSymbolAddress((void**)&gk,  g_K);
    cudaGetSymbolAddress((void**)&gv,  g_V);
    cudaGetSymbolAddress((void**)&gao, g_AO);
    cudaGetSymbolAddress((void**)&wwq, g_Wq);
    cudaGetSymbolAddress((void**)&wwk, g_Wk);
    cudaGetSymbolAddress((void**)&wwv, g_Wv);
    cudaGetSymbolAddress((void**)&wwo, g_Wo);

    cudaFuncSetAttribute(flash_mma_kernel,
                         cudaFuncAttributeMaxDynamicSharedMemorySize, ATT_SMEM);
    cudaFuncSetAttribute(gemm_hmma,
                         cudaFuncAttributeMaxDynamicSharedMemorySize, G_SMEM);

    // ---- weight rounding prepass (activations rounded in-kernel) ----
    const int nW4 = DD * DD / 4;
    round_tf32_kernel<<<(nW4 + 255) / 256, 256>>>(wq, wwq, nW4);
    round_tf32_kernel<<<(nW4 + 255) / 256, 256>>>(wk, wwk, nW4);
    round_tf32_kernel<<<(nW4 + 255) / 256, 256>>>(wv, wwv, nW4);
    round_tf32_kernel<<<(nW4 + 255) / 256, 256>>>(wo, wwo, nW4);

    dim3 gblk(256);
    dim3 ggrid(DD / 128, MTOT / 128);   // (8, 64)

    gemm_hmma<<<ggrid, gblk, G_SMEM>>>(q, wwq, bq, gq, MTOT, DD, DD);
    gemm_hmma<<<ggrid, gblk, G_SMEM>>>(k, wwk, bk, gk, MTOT, DD, DD);
    gemm_hmma<<<ggrid, gblk, G_SMEM>>>(v, wwv, bv, gv, MTOT, DD, DD);

    dim3 agrid(SS / 128, HH, BB);       // (16, 16, 4)
    flash_mma_kernel<<<agrid, dim3(128), ATT_SMEM>>>(gq, gk, gv, gao);

    gemm_hmma<<<ggrid, gblk, G_SMEM>>>(gao, wwo, bo, out, MTOT, DD, DD);
}